// round 4
// baseline (speedup 1.0000x reference)
#include <cuda_runtime.h>
#include <math.h>

#define H 4096
#define IDIM 5632
#define NE 8
#define T 4096
#define NTOPK 2
#define NSLOTS (T * NTOPK)

// ---------------- scratch (device globals; allocation-free) ----------------
__device__ float g_act[(size_t)NSLOTS * IDIM];   // silu(g)*u activations, expert-sorted slots
__device__ int   g_counts[NE];
__device__ int   g_offsets[NE];
__device__ int   g_cursor[NE];
__device__ int   g_topi[T * NTOPK];
__device__ float g_topw[T * NTOPK];
__device__ int   g_tok[NSLOTS];                  // slot -> token
__device__ float g_sw[NSLOTS];                   // slot -> routing weight
__device__ float g_psum[NE];                     // sum of softmax probs per expert
__device__ float g_zsum;                         // sum of lse^2

// ---------------- reset ----------------
__global__ void reset_kernel() {
    int i = threadIdx.x;
    if (i < NE) { g_counts[i] = 0; g_cursor[i] = 0; g_psum[i] = 0.f; }
    if (i == 0) g_zsum = 0.f;
}

// ---------------- router: logits, softmax, top-2, aux stats ----------------
__global__ void router_kernel(const float* __restrict__ x,
                              const float* __restrict__ Wgate) {
    int t = blockIdx.x;
    const float* xr = x + (size_t)t * H;
    float p[NE];
#pragma unroll
    for (int e = 0; e < NE; ++e) p[e] = 0.f;

    for (int c = threadIdx.x; c < H; c += blockDim.x) {
        float xv = xr[c];
#pragma unroll
        for (int e = 0; e < NE; ++e) p[e] += xv * Wgate[e * H + c];
    }

    __shared__ float sm[NE][128];
#pragma unroll
    for (int e = 0; e < NE; ++e) sm[e][threadIdx.x] = p[e];
    __syncthreads();
    for (int s = 64; s > 0; s >>= 1) {
        if (threadIdx.x < s) {
#pragma unroll
            for (int e = 0; e < NE; ++e)
                sm[e][threadIdx.x] += sm[e][threadIdx.x + s];
        }
        __syncthreads();
    }

    if (threadIdx.x == 0) {
        float lg[NE];
#pragma unroll
        for (int e = 0; e < NE; ++e) lg[e] = sm[e][0];
        float mx = lg[0];
#pragma unroll
        for (int e = 1; e < NE; ++e) mx = fmaxf(mx, lg[e]);
        float se = 0.f, pr[NE];
#pragma unroll
        for (int e = 0; e < NE; ++e) { pr[e] = expf(lg[e] - mx); se += pr[e]; }
        float inv = 1.f / se;
#pragma unroll
        for (int e = 0; e < NE; ++e) pr[e] *= inv;

        // top-2 (lowest index wins ties, matching lax.top_k)
        int i0 = 0;
#pragma unroll
        for (int e = 1; e < NE; ++e) if (pr[e] > pr[i0]) i0 = e;
        int i1 = (i0 == 0) ? 1 : 0;
#pragma unroll
        for (int e = 0; e < NE; ++e)
            if (e != i0 && pr[e] > pr[i1]) i1 = e;

        float w0 = pr[i0], w1 = pr[i1];
        float ws = 1.f / (w0 + w1);
        w0 *= ws; w1 *= ws;

        g_topi[2 * t + 0] = i0; g_topw[2 * t + 0] = w0;
        g_topi[2 * t + 1] = i1; g_topw[2 * t + 1] = w1;
        atomicAdd(&g_counts[i0], 1);
        atomicAdd(&g_counts[i1], 1);
#pragma unroll
        for (int e = 0; e < NE; ++e) atomicAdd(&g_psum[e], pr[e]);
        float lse = mx + logf(se);
        atomicAdd(&g_zsum, lse * lse);
    }
}

// ---------------- finalize: offsets + aux scalar ----------------
__global__ void finalize_kernel(float* __restrict__ out, int out_size) {
    if (threadIdx.x == 0 && blockIdx.x == 0) {
        int off = 0;
        for (int e = 0; e < NE; ++e) {
            g_offsets[e] = off;
            g_cursor[e] = off;
            off += g_counts[e];
        }
        float aux = 0.f;
        for (int e = 0; e < NE; ++e) {
            float pm = g_psum[e] / (float)T;
            float fr = (float)g_counts[e] / (float)(T * NTOPK);
            aux += pm * fr;
        }
        aux *= (float)NE;
        float z = g_zsum / (float)T;
        float total = 0.02f * aux + 0.001f * z;
        if (out_size > T * H) out[(size_t)T * H] = total;
    }
}

// ---------------- slot assignment ----------------
__global__ void assign_kernel() {
    int t = blockIdx.x * blockDim.x + threadIdx.x;
    if (t >= T) return;
#pragma unroll
    for (int k = 0; k < NTOPK; ++k) {
        int e = g_topi[2 * t + k];
        int s = atomicAdd(&g_cursor[e], 1);
        g_tok[s] = t;
        g_sw[s] = g_topw[2 * t + k];
    }
}

// ---------------- GEMM1: act = silu(X_e @ Wg[e]^T) * (X_e @ Wu[e]^T) -------
// BM=128, BN=64, BK=16, 256 threads; dual accumulator (gate+up)
#define BM 128
#define BN 64
#define BK 16

__global__ __launch_bounds__(256)
void gemm1_kernel(const float* __restrict__ x,
                  const float* __restrict__ Wg,
                  const float* __restrict__ Wu) {
    int e = blockIdx.z;
    int cnt = g_counts[e];
    int m0 = blockIdx.x * BM;
    if (m0 >= cnt) return;
    int base = g_offsets[e];
    int n0 = blockIdx.y * BN;

    const float* Bgp = Wg + (size_t)e * IDIM * H + (size_t)n0 * H;
    const float* Bup = Wu + (size_t)e * IDIM * H + (size_t)n0 * H;

    __shared__ float As[BK][BM + 4];
    __shared__ float Bgs[BK][BN + 4];
    __shared__ float Bus[BK][BN + 4];

    int tid = threadIdx.x;
    int kq = tid & 3;               // which float4 within the 16-wide k slab
    int ar0 = tid >> 2;             // A rows: tid/4 and tid/4 + 64
    int ar1 = ar0 + 64;
    int brow = tid >> 2;            // B row 0..63

    // Row pointers (gathered tokens); null => zero-fill
    const float* ap0 = nullptr;
    const float* ap1 = nullptr;
    if (m0 + ar0 < cnt) ap0 = x + (size_t)g_tok[base + m0 + ar0] * H + kq * 4;
    if (m0 + ar1 < cnt) ap1 = x + (size_t)g_tok[base + m0 + ar1] * H + kq * 4;
    const float* bgp = Bgp + (size_t)brow * H + kq * 4;
    const float* bup = Bup + (size_t)brow * H + kq * 4;

    int tx = tid & 15;              // n sub 0..15 (4 cols each)
    int ty = tid >> 4;              // m sub 0..15 (8 rows each)

    float accg[8][4], accu[8][4];
#pragma unroll
    for (int i = 0; i < 8; ++i)
#pragma unroll
        for (int j = 0; j < 4; ++j) { accg[i][j] = 0.f; accu[i][j] = 0.f; }

    for (int k0 = 0; k0 < H; k0 += BK) {
        float4 a0 = make_float4(0.f, 0.f, 0.f, 0.f);
        float4 a1 = make_float4(0.f, 0.f, 0.f, 0.f);
        if (ap0) a0 = *(const float4*)(ap0 + k0);
        if (ap1) a1 = *(const float4*)(ap1 + k0);
        float4 bg = *(const float4*)(bgp + k0);
        float4 bu = *(const float4*)(bup + k0);

        As[kq * 4 + 0][ar0] = a0.x; As[kq * 4 + 1][ar0] = a0.y;
        As[kq * 4 + 2][ar0] = a0.z; As[kq * 4 + 3][ar0] = a0.w;
        As[kq * 4 + 0][ar1] = a1.x; As[kq * 4 + 1][ar1] = a1.y;
        As[kq * 4 + 2][ar1] = a1.z; As[kq * 4 + 3][ar1] = a1.w;
        Bgs[kq * 4 + 0][brow] = bg.x; Bgs[kq * 4 + 1][brow] = bg.y;
        Bgs[kq * 4 + 2][brow] = bg.z; Bgs[kq * 4 + 3][brow] = bg.w;
        Bus[kq * 4 + 0][brow] = bu.x; Bus[kq * 4 + 1][brow] = bu.y;
        Bus[kq * 4 + 2][brow] = bu.z; Bus[kq * 4 + 3][brow] = bu.w;
        __syncthreads();

#pragma unroll
        for (int k = 0; k < BK; ++k) {
            float av[8];
#pragma unroll
            for (int i = 0; i < 8; ++i) av[i] = As[k][ty * 8 + i];
            float bgv[4], buv[4];
#pragma unroll
            for (int j = 0; j < 4; ++j) {
                bgv[j] = Bgs[k][tx * 4 + j];
                buv[j] = Bus[k][tx * 4 + j];
            }
#pragma unroll
            for (int i = 0; i < 8; ++i)
#pragma unroll
                for (int j = 0; j < 4; ++j) {
                    accg[i][j] = fmaf(av[i], bgv[j], accg[i][j]);
                    accu[i][j] = fmaf(av[i], buv[j], accu[i][j]);
                }
        }
        __syncthreads();
    }

    // epilogue: silu(g)*u -> act scratch
#pragma unroll
    for (int i = 0; i < 8; ++i) {
        int r = m0 + ty * 8 + i;
        if (r < cnt) {
            float* dst = g_act + (size_t)(base + r) * IDIM + n0 + tx * 4;
            float4 v;
            float g0 = accg[i][0], g1 = accg[i][1], g2 = accg[i][2], g3 = accg[i][3];
            v.x = (g0 / (1.f + expf(-g0))) * accu[i][0];
            v.y = (g1 / (1.f + expf(-g1))) * accu[i][1];
            v.z = (g2 / (1.f + expf(-g2))) * accu[i][2];
            v.w = (g3 / (1.f + expf(-g3))) * accu[i][3];
            *(float4*)dst = v;
        }
    }
}

// ---------------- GEMM2: out[tok] += w * (act_e @ Wd[e]^T) ------------------
__global__ __launch_bounds__(256)
void gemm2_kernel(const float* __restrict__ Wd, float* __restrict__ out) {
    int e = blockIdx.z;
    int cnt = g_counts[e];
    int m0 = blockIdx.x * BM;
    if (m0 >= cnt) return;
    int base = g_offsets[e];
    int n0 = blockIdx.y * BN;

    const float* Bp = Wd + (size_t)e * H * IDIM + (size_t)n0 * IDIM;

    __shared__ float As[BK][BM + 4];
    __shared__ float Bs[BK][BN + 4];

    int tid = threadIdx.x;
    int kq = tid & 3;
    int ar0 = tid >> 2;
    int ar1 = ar0 + 64;
    int brow = tid >> 2;

    const float* ap0 = nullptr;
    const float* ap1 = nullptr;
    if (m0 + ar0 < cnt) ap0 = g_act + (size_t)(base + m0 + ar0) * IDIM + kq * 4;
    if (m0 + ar1 < cnt) ap1 = g_act + (size_t)(base + m0 + ar1) * IDIM + kq * 4;
    const float* bp = Bp + (size_t)brow * IDIM + kq * 4;

    int tx = tid & 15;
    int ty = tid >> 4;

    float acc[8][4];
#pragma unroll
    for (int i = 0; i < 8; ++i)
#pragma unroll
        for (int j = 0; j < 4; ++j) acc[i][j] = 0.f;

    for (int k0 = 0; k0 < IDIM; k0 += BK) {
        float4 a0 = make_float4(0.f, 0.f, 0.f, 0.f);
        float4 a1 = make_float4(0.f, 0.f, 0.f, 0.f);
        if (ap0) a0 = *(const float4*)(ap0 + k0);
        if (ap1) a1 = *(const float4*)(ap1 + k0);
        float4 b = *(const float4*)(bp + k0);

        As[kq * 4 + 0][ar0] = a0.x; As[kq * 4 + 1][ar0] = a0.y;
        As[kq * 4 + 2][ar0] = a0.z; As[kq * 4 + 3][ar0] = a0.w;
        As[kq * 4 + 0][ar1] = a1.x; As[kq * 4 + 1][ar1] = a1.y;
        As[kq * 4 + 2][ar1] = a1.z; As[kq * 4 + 3][ar1] = a1.w;
        Bs[kq * 4 + 0][brow] = b.x; Bs[kq * 4 + 1][brow] = b.y;
        Bs[kq * 4 + 2][brow] = b.z; Bs[kq * 4 + 3][brow] = b.w;
        __syncthreads();

#pragma unroll
        for (int k = 0; k < BK; ++k) {
            float av[8];
#pragma unroll
            for (int i = 0; i < 8; ++i) av[i] = As[k][ty * 8 + i];
            float bv[4];
#pragma unroll
            for (int j = 0; j < 4; ++j) bv[j] = Bs[k][tx * 4 + j];
#pragma unroll
            for (int i = 0; i < 8; ++i)
#pragma unroll
                for (int j = 0; j < 4; ++j)
                    acc[i][j] = fmaf(av[i], bv[j], acc[i][j]);
        }
        __syncthreads();
    }

#pragma unroll
    for (int i = 0; i < 8; ++i) {
        int r = m0 + ty * 8 + i;
        if (r < cnt) {
            int s = base + r;
            int tok = g_tok[s];
            float w = g_sw[s];
            float* dst = out + (size_t)tok * H + n0 + tx * 4;
#pragma unroll
            for (int j = 0; j < 4; ++j)
                atomicAdd(dst + j, w * acc[i][j]);
        }
    }
}

// ---------------- launch ----------------
extern "C" void kernel_launch(void* const* d_in, const int* in_sizes, int n_in,
                              void* d_out, int out_size) {
    const float* x     = (const float*)d_in[0];   // [2,2048,H] fp32
    const float* Wgate = (const float*)d_in[1];   // [E,H]
    const float* Wg    = (const float*)d_in[2];   // [E,I,H]
    const float* Wu    = (const float*)d_in[3];   // [E,I,H]
    const float* Wd    = (const float*)d_in[4];   // [E,H,I]
    float* out = (float*)d_out;

    cudaMemsetAsync(out, 0, (size_t)out_size * sizeof(float));
    reset_kernel<<<1, 32>>>();
    router_kernel<<<T, 128>>>(x, Wgate);
    finalize_kernel<<<1, 32>>>(out, out_size);
    assign_kernel<<<(T + 255) / 256, 256>>>();

    // M fastest in grid.x so concurrent blocks share the same weight tile (L2 reuse)
    dim3 g1(T / BM, IDIM / BN, NE);          // (32, 88, 8)
    gemm1_kernel<<<g1, 256>>>(x, Wg, Wu);

    dim3 g2(T / BM, H / BN, NE);             // (32, 64, 8)
    gemm2_kernel<<<g2, 256>>>(Wd, out);
}

// round 6
// speedup vs baseline: 2.1050x; 2.1050x over previous
#include <cuda_runtime.h>
#include <cuda_bf16.h>
#include <math.h>

typedef unsigned int u32;

#define H 4096
#define IDIM 5632
#define NE 8
#define T 4096
#define NSLOTS (T * 2)
#define BM 128
#define BN 128
#define BK 32
#define SMEMSZ (1024 + 2 * 32768)

// ---------------- scratch (device globals; allocation-free) ----------------
__device__ float g_tmp[(size_t)NSLOTS * IDIM];   // raw gate values
__device__ float g_act[(size_t)NSLOTS * IDIM];   // silu(g)*u
__device__ int   g_counts[NE];
__device__ int   g_offsets[NE];
__device__ int   g_cursor[NE];
__device__ int   g_topi[T * 2];
__device__ float g_topw[T * 2];
__device__ int   g_tok[NSLOTS];
__device__ float g_sw[NSLOTS];
__device__ float g_psum[NE];
__device__ float g_zsum;

// ---------------- helpers ----------------
__device__ __forceinline__ u32 smem_u32(const void* p) {
    u32 a;
    asm("{ .reg .u64 t; cvta.to.shared.u64 t, %1; cvt.u32.u64 %0, t; }" : "=r"(a) : "l"(p));
    return a;
}
// row-major bf16 tile [128][32], 64B rows of 4 16B chunks, XOR swizzle
__device__ __forceinline__ u32 swoff(int row, int ch) {
    return (u32)(row * 64 + ((ch ^ ((row >> 1) & 3)) << 4));
}
__device__ __forceinline__ u32 prmt_hi(float a, float b) {  // low=bf16(a) trunc, high=bf16(b)
    u32 r;
    asm("prmt.b32 %0, %1, %2, 0x7632;" : "=r"(r) : "r"(__float_as_uint(a)), "r"(__float_as_uint(b)));
    return r;
}
__device__ __forceinline__ float resid(float a) {
    return a - __uint_as_float(__float_as_uint(a) & 0xFFFF0000u);
}
__device__ __forceinline__ u32 pack_lo(float a, float b) {  // low=bf16rn(a), high=bf16rn(b)
    u32 r;
    asm("cvt.rn.bf16x2.f32 %0, %1, %2;" : "=r"(r) : "f"(b), "f"(a));
    return r;
}
__device__ __forceinline__ void sts8(u32 hi_a, u32 lo_a, float4 v0, float4 v1) {
    u32 h0 = prmt_hi(v0.x, v0.y), h1 = prmt_hi(v0.z, v0.w);
    u32 h2 = prmt_hi(v1.x, v1.y), h3 = prmt_hi(v1.z, v1.w);
    u32 l0 = pack_lo(resid(v0.x), resid(v0.y)), l1 = pack_lo(resid(v0.z), resid(v0.w));
    u32 l2 = pack_lo(resid(v1.x), resid(v1.y)), l3 = pack_lo(resid(v1.z), resid(v1.w));
    asm volatile("st.shared.v4.b32 [%0], {%1,%2,%3,%4};" :: "r"(hi_a), "r"(h0), "r"(h1), "r"(h2), "r"(h3) : "memory");
    asm volatile("st.shared.v4.b32 [%0], {%1,%2,%3,%4};" :: "r"(lo_a), "r"(l0), "r"(l1), "r"(l2), "r"(l3) : "memory");
}
#define LDSM4(R, A)                                                             \
    asm volatile("ldmatrix.sync.aligned.m8n8.x4.shared.b16 {%0,%1,%2,%3}, [%4];" \
        : "=r"((R)[0]), "=r"((R)[1]), "=r"((R)[2]), "=r"((R)[3]) : "r"(A))

__device__ __forceinline__ void mma16816(float* d, const u32* a, const u32* b) {
    asm volatile(
        "mma.sync.aligned.m16n8k16.row.col.f32.bf16.bf16.f32 "
        "{%0,%1,%2,%3},{%4,%5,%6,%7},{%8,%9},{%0,%1,%2,%3};"
        : "+f"(d[0]), "+f"(d[1]), "+f"(d[2]), "+f"(d[3])
        : "r"(a[0]), "r"(a[1]), "r"(a[2]), "r"(a[3]), "r"(b[0]), "r"(b[1]));
}

// ---------------- small kernels ----------------
__global__ void reset_kernel() {
    int i = threadIdx.x;
    if (i < NE) { g_counts[i] = 0; g_cursor[i] = 0; g_psum[i] = 0.f; }
    if (i == 0) g_zsum = 0.f;
}

__global__ void router_kernel(const float* __restrict__ x,
                              const float* __restrict__ Wgate) {
    int t = blockIdx.x;
    const float* xr = x + (size_t)t * H;
    float p[NE];
#pragma unroll
    for (int e = 0; e < NE; ++e) p[e] = 0.f;
    for (int c = threadIdx.x; c < H; c += blockDim.x) {
        float xv = xr[c];
#pragma unroll
        for (int e = 0; e < NE; ++e) p[e] += xv * Wgate[e * H + c];
    }
    __shared__ float sm[NE][128];
#pragma unroll
    for (int e = 0; e < NE; ++e) sm[e][threadIdx.x] = p[e];
    __syncthreads();
    for (int s = 64; s > 0; s >>= 1) {
        if (threadIdx.x < s)
#pragma unroll
            for (int e = 0; e < NE; ++e)
                sm[e][threadIdx.x] += sm[e][threadIdx.x + s];
        __syncthreads();
    }
    if (threadIdx.x == 0) {
        float lg[NE];
#pragma unroll
        for (int e = 0; e < NE; ++e) lg[e] = sm[e][0];
        float mx = lg[0];
#pragma unroll
        for (int e = 1; e < NE; ++e) mx = fmaxf(mx, lg[e]);
        float se = 0.f, pr[NE];
#pragma unroll
        for (int e = 0; e < NE; ++e) { pr[e] = expf(lg[e] - mx); se += pr[e]; }
        float inv = 1.f / se;
#pragma unroll
        for (int e = 0; e < NE; ++e) pr[e] *= inv;
        int i0 = 0;
#pragma unroll
        for (int e = 1; e < NE; ++e) if (pr[e] > pr[i0]) i0 = e;
        int i1 = (i0 == 0) ? 1 : 0;
#pragma unroll
        for (int e = 0; e < NE; ++e)
            if (e != i0 && pr[e] > pr[i1]) i1 = e;
        float w0 = pr[i0], w1 = pr[i1];
        float ws = 1.f / (w0 + w1);
        g_topi[2 * t] = i0;     g_topw[2 * t] = w0 * ws;
        g_topi[2 * t + 1] = i1; g_topw[2 * t + 1] = w1 * ws;
        atomicAdd(&g_counts[i0], 1);
        atomicAdd(&g_counts[i1], 1);
#pragma unroll
        for (int e = 0; e < NE; ++e) atomicAdd(&g_psum[e], pr[e]);
        float lse = mx + logf(se);
        atomicAdd(&g_zsum, lse * lse);
    }
}

__global__ void finalize_kernel(float* __restrict__ out, int out_size) {
    if (threadIdx.x == 0 && blockIdx.x == 0) {
        int off = 0;
        for (int e = 0; e < NE; ++e) { g_offsets[e] = off; g_cursor[e] = off; off += g_counts[e]; }
        float aux = 0.f;
        for (int e = 0; e < NE; ++e)
            aux += (g_psum[e] / (float)T) * ((float)g_counts[e] / (float)(T * 2));
        aux *= (float)NE;
        float z = g_zsum / (float)T;
        if (out_size > T * H) out[(size_t)T * H] = 0.02f * aux + 0.001f * z;
    }
}

__global__ void assign_kernel() {
    int t = blockIdx.x * blockDim.x + threadIdx.x;
    if (t >= T) return;
#pragma unroll
    for (int k = 0; k < 2; ++k) {
        int e = g_topi[2 * t + k];
        int s = atomicAdd(&g_cursor[e], 1);
        g_tok[s] = t;
        g_sw[s] = g_topw[2 * t + k];
    }
}

// ---------------- unified split-bf16 MMA GEMM ----------------
// MODE 0: A=x(gather), B=Wg  -> g_tmp (raw gate)
// MODE 1: A=x(gather), B=Wu  -> g_act = silu(g_tmp)*u
// MODE 2: A=g_act,     B=Wd  -> out[tok] += w * result (atomic)
template <int MODE>
__global__ __launch_bounds__(256)
void gemm_kernel(const float* __restrict__ Asrc, const float* __restrict__ W,
                 float* __restrict__ outp) {
    constexpr int KD = (MODE == 2) ? IDIM : H;
    constexpr int KT = KD / BK;

    int e = blockIdx.z;
    int cnt = g_counts[e];
    int m0 = blockIdx.x * BM;
    if (m0 >= cnt) return;
    int base = g_offsets[e];
    int n0 = blockIdx.y * BN;

    extern __shared__ char smem[];
    const float** aptr = (const float**)smem;   // 128 row pointers (1 KB)
    u32 tiles = smem_u32(smem) + 1024;          // 2 stages x 32 KB

    int tid = threadIdx.x, lane = tid & 31, wid = tid >> 5;
    int wm = wid & 3, wn = wid >> 2;

    if (tid < 128) {
        int r = m0 + tid;
        int slot = base + ((r < cnt) ? r : (cnt - 1));
        aptr[tid] = (MODE == 2) ? (g_act + (size_t)slot * IDIM)
                                : (Asrc + (size_t)g_tok[slot] * H);
    }
    __syncthreads();

    const float* wB = W + (size_t)e * ((size_t)IDIM * H) + (size_t)n0 * KD;

    int lr = tid >> 1;           // loader row 0..127
    int lc = (tid & 1) * 2;      // chunk base (chunk = 8 elems)
    const float* aRow = aptr[lr] + lc * 8;
    const float* bRow = wB + (size_t)lr * KD + lc * 8;
    u32 sA0 = swoff(lr, lc), sA1 = swoff(lr, lc + 1);

    // preload stage 0
    {
        float4 a0 = *(const float4*)(aRow);
        float4 a1 = *(const float4*)(aRow + 4);
        float4 a2 = *(const float4*)(aRow + 8);
        float4 a3 = *(const float4*)(aRow + 12);
        float4 b0 = *(const float4*)(bRow);
        float4 b1 = *(const float4*)(bRow + 4);
        float4 b2 = *(const float4*)(bRow + 8);
        float4 b3 = *(const float4*)(bRow + 12);
        sts8(tiles + sA0, tiles + 8192 + sA0, a0, a1);
        sts8(tiles + sA1, tiles + 8192 + sA1, a2, a3);
        sts8(tiles + 16384 + sA0, tiles + 24576 + sA0, b0, b1);
        sts8(tiles + 16384 + sA1, tiles + 24576 + sA1, b2, b3);
    }
    __syncthreads();

    float acc[2][8][4];
#pragma unroll
    for (int i = 0; i < 2; ++i)
#pragma unroll
        for (int j = 0; j < 8; ++j)
#pragma unroll
            for (int c = 0; c < 4; ++c) acc[i][j][c] = 0.f;

#pragma unroll 1
    for (int kt = 0; kt < KT; ++kt) {
        int b = kt & 1;
        u32 stage = tiles + b * 32768;

        float4 pa0, pa1, pa2, pa3, pb0, pb1, pb2, pb3;
        bool pf = (kt + 1 < KT);
        if (pf) {
            int k0 = (kt + 1) * BK;
            pa0 = *(const float4*)(aRow + k0);
            pa1 = *(const float4*)(aRow + k0 + 4);
            pa2 = *(const float4*)(aRow + k0 + 8);
            pa3 = *(const float4*)(aRow + k0 + 12);
            pb0 = *(const float4*)(bRow + k0);
            pb1 = *(const float4*)(bRow + k0 + 4);
            pb2 = *(const float4*)(bRow + k0 + 8);
            pb3 = *(const float4*)(bRow + k0 + 12);
        }

#pragma unroll
        for (int ks = 0; ks < 2; ++ks) {
            u32 Ah[2][4], Al[2][4];
#pragma unroll
            for (int mi = 0; mi < 2; ++mi) {
                int row = wm * 32 + mi * 16 + (lane & 15);
                int ch = ks * 2 + (lane >> 4);
                u32 off = swoff(row, ch);
                LDSM4(Ah[mi], stage + off);
                LDSM4(Al[mi], stage + 8192 + off);
            }
#pragma unroll
            for (int p = 0; p < 4; ++p) {
                int row = wn * 64 + p * 16 + ((lane >> 4) << 3) + (lane & 7);
                int ch = ks * 2 + ((lane >> 3) & 1);
                u32 off = swoff(row, ch);
                u32 Bh[4], Bl[4];
                LDSM4(Bh, stage + 16384 + off);
                LDSM4(Bl, stage + 24576 + off);
#pragma unroll
                for (int mi = 0; mi < 2; ++mi) {
                    mma16816(acc[mi][2 * p],     Ah[mi], Bh);
                    mma16816(acc[mi][2 * p + 1], Ah[mi], Bh + 2);
                    mma16816(acc[mi][2 * p],     Ah[mi], Bl);
                    mma16816(acc[mi][2 * p + 1], Ah[mi], Bl + 2);
                    mma16816(acc[mi][2 * p],     Al[mi], Bh);
                    mma16816(acc[mi][2 * p + 1], Al[mi], Bh + 2);
                }
            }
        }

        if (pf) {
            u32 ns = tiles + (b ^ 1) * 32768;
            sts8(ns + sA0, ns + 8192 + sA0, pa0, pa1);
            sts8(ns + sA1, ns + 8192 + sA1, pa2, pa3);
            sts8(ns + 16384 + sA0, ns + 24576 + sA0, pb0, pb1);
            sts8(ns + 16384 + sA1, ns + 24576 + sA1, pb2, pb3);
        }
        __syncthreads();
    }

    // epilogue
    int rA = m0 + wm * 32 + (lane >> 2);
    int cA = n0 + wn * 64 + (lane & 3) * 2;
#pragma unroll
    for (int mi = 0; mi < 2; ++mi) {
#pragma unroll
        for (int ni = 0; ni < 8; ++ni) {
            int col = cA + ni * 8;
#pragma unroll
            for (int h = 0; h < 2; ++h) {
                int r = rA + mi * 16 + h * 8;
                if (r >= cnt) continue;
                float v0 = acc[mi][ni][2 * h], v1 = acc[mi][ni][2 * h + 1];
                int slot = base + r;
                if (MODE == 0) {
                    float2 o; o.x = v0; o.y = v1;
                    *(float2*)(g_tmp + (size_t)slot * IDIM + col) = o;
                } else if (MODE == 1) {
                    float2 g = *(const float2*)(g_tmp + (size_t)slot * IDIM + col);
                    float2 o;
                    o.x = g.x / (1.f + __expf(-g.x)) * v0;
                    o.y = g.y / (1.f + __expf(-g.y)) * v1;
                    *(float2*)(g_act + (size_t)slot * IDIM + col) = o;
                } else {
                    float w = g_sw[slot];
                    float* d = outp + (size_t)g_tok[slot] * H + col;
                    atomicAdd(d, w * v0);
                    atomicAdd(d + 1, w * v1);
                }
            }
        }
    }
}

// ---------------- launch ----------------
extern "C" void kernel_launch(void* const* d_in, const int* in_sizes, int n_in,
                              void* d_out, int out_size) {
    const float* x     = (const float*)d_in[0];
    const float* Wgate = (const float*)d_in[1];
    const float* Wg    = (const float*)d_in[2];
    const float* Wu    = (const float*)d_in[3];
    const float* Wd    = (const float*)d_in[4];
    float* out = (float*)d_out;

    cudaFuncSetAttribute(gemm_kernel<0>, cudaFuncAttributeMaxDynamicSharedMemorySize, SMEMSZ);
    cudaFuncSetAttribute(gemm_kernel<1>, cudaFuncAttributeMaxDynamicSharedMemorySize, SMEMSZ);
    cudaFuncSetAttribute(gemm_kernel<2>, cudaFuncAttributeMaxDynamicSharedMemorySize, SMEMSZ);

    cudaMemsetAsync(out, 0, (size_t)out_size * sizeof(float));
    reset_kernel<<<1, 32>>>();
    router_kernel<<<T, 128>>>(x, Wgate);
    finalize_kernel<<<1, 32>>>(out, out_size);
    assign_kernel<<<(T + 255) / 256, 256>>>();

    dim3 g1(T / BM, IDIM / BN, NE);   // (32, 44, 8)
    gemm_kernel<0><<<g1, 256, SMEMSZ>>>(x, Wg, out);
    gemm_kernel<1><<<g1, 256, SMEMSZ>>>(x, Wu, out);

    dim3 g2(T / BM, H / BN, NE);      // (32, 32, 8)
    gemm_kernel<2><<<g2, 256, SMEMSZ>>>(x, Wd, out);
}